// round 1
// baseline (speedup 1.0000x reference)
#include <cuda_runtime.h>
#include <cuda_bf16.h>
#include <cstddef>

#define NN 50000
#define NE 800000

// ---------------- scratch (static device globals; no allocation) ----------------
__device__ int   g_cnt[NN];
__device__ int   g_rowptr[NN + 1];
__device__ int   g_wr[NN];
__device__ int   g_csr[NE];
__device__ float g_dinv[NN];
__device__ float g_tl[(size_t)NN * 128];   // pre-transformed (to be aggregated)
__device__ float g_tr[(size_t)NN * 128];   // self-transform + bias
__device__ float g_h1[(size_t)NN * 128];
__device__ float g_h2[(size_t)NN * 128];

// ---------------- CSR build ----------------
__global__ void zero_cnt_kernel() {
    int i = blockIdx.x * blockDim.x + threadIdx.x;
    if (i < NN) g_cnt[i] = 0;
}

__global__ void hist_kernel(const int* __restrict__ dst) {
    int e = blockIdx.x * blockDim.x + threadIdx.x;
    if (e < NE) atomicAdd(&g_cnt[dst[e]], 1);
}

__global__ void scan_kernel() {
    __shared__ int sm[1024];
    int t = threadIdx.x;
    const int CH = 49;  // 1024*49 = 50176 >= 50000
    int base = t * CH;
    int s = 0;
    for (int j = 0; j < CH; j++) {
        int i = base + j;
        if (i < NN) s += g_cnt[i];
    }
    sm[t] = s;
    __syncthreads();
    // inclusive Hillis-Steele scan
    for (int off = 1; off < 1024; off <<= 1) {
        int v = (t >= off) ? sm[t - off] : 0;
        __syncthreads();
        sm[t] += v;
        __syncthreads();
    }
    int run = (t == 0) ? 0 : sm[t - 1];
    for (int j = 0; j < CH; j++) {
        int i = base + j;
        if (i < NN) {
            g_rowptr[i] = run;
            g_wr[i] = run;
            int c = g_cnt[i];
            g_dinv[i] = 1.0f / (float)((c > 1) ? c : 1);
            run += c;
        }
    }
    if (t == 0) g_rowptr[NN] = NE;
}

__global__ void scatter_kernel(const int* __restrict__ src, const int* __restrict__ dst) {
    int e = blockIdx.x * blockDim.x + threadIdx.x;
    if (e < NE) {
        int p = atomicAdd(&g_wr[dst[e]], 1);
        g_csr[p] = src[e];
    }
}

// ---------------- SGEMM: Y = X[M,128] @ W[128,HOUT] (+bias on the "right" path) ----------------
// blockIdx.y = 0 -> W = Wl, Y = Yl, no bias
// blockIdx.y = 1 -> W = Wr, Y = Yr, +bias
template <int HOUT>
__global__ void __launch_bounds__(256) gemm2_kernel(
    const float* __restrict__ X,
    const float* __restrict__ Wl, const float* __restrict__ Wr,
    const float* __restrict__ bias,
    float* __restrict__ Yl, float* __restrict__ Yr, int M)
{
    const float* W = blockIdx.y ? Wr : Wl;
    float* Y       = blockIdx.y ? Yr : Yl;
    const float* B = blockIdx.y ? bias : nullptr;

    constexpr int KT = 32;
    constexpr int RN = HOUT / 16;            // 8 for 128, 4 for 64
    __shared__ float As[KT][132];            // A stored transposed: As[k][m]
    __shared__ float Bs[KT][HOUT + 4];

    int tid = threadIdx.x;
    int tx = tid & 15, ty = tid >> 4;
    int m0 = blockIdx.x * 128;

    float acc[8][RN];
#pragma unroll
    for (int i = 0; i < 8; i++)
#pragma unroll
        for (int j = 0; j < RN; j++) acc[i][j] = 0.f;

    for (int kc = 0; kc < 128; kc += KT) {
        // load A tile 128x32, transpose into smem
#pragma unroll
        for (int l = 0; l < 4; l++) {
            int idx = tid + l * 256;          // 0..1023 float4 slots
            int r = idx >> 3;                 // row 0..127
            int c4 = idx & 7;                 // float4 within k-chunk
            float4 v = make_float4(0.f, 0.f, 0.f, 0.f);
            int gr = m0 + r;
            if (gr < M) v = *(const float4*)(X + (size_t)gr * 128 + kc + c4 * 4);
            As[c4 * 4 + 0][r] = v.x;
            As[c4 * 4 + 1][r] = v.y;
            As[c4 * 4 + 2][r] = v.z;
            As[c4 * 4 + 3][r] = v.w;
        }
        // load B tile 32 x HOUT
        constexpr int BL = (KT * HOUT) / (4 * 256);   // 4 or 2
#pragma unroll
        for (int l = 0; l < BL; l++) {
            int idx = tid + l * 256;
            int r = idx / (HOUT / 4);
            int c4 = idx % (HOUT / 4);
            float4 v = *(const float4*)(W + (size_t)(kc + r) * HOUT + c4 * 4);
            *(float4*)&Bs[r][c4 * 4] = v;
        }
        __syncthreads();

#pragma unroll
        for (int k = 0; k < KT; k++) {
            float a[8], b[RN];
            *(float4*)&a[0] = *(const float4*)&As[k][ty * 8];
            *(float4*)&a[4] = *(const float4*)&As[k][ty * 8 + 4];
#pragma unroll
            for (int j = 0; j < RN; j += 4)
                *(float4*)&b[j] = *(const float4*)&Bs[k][tx * RN + j];
#pragma unroll
            for (int i = 0; i < 8; i++)
#pragma unroll
                for (int j = 0; j < RN; j++)
                    acc[i][j] += a[i] * b[j];
        }
        __syncthreads();
    }

#pragma unroll
    for (int i = 0; i < 8; i++) {
        int gr = m0 + ty * 8 + i;
        if (gr >= M) continue;
#pragma unroll
        for (int j = 0; j < RN; j += 4) {
            float4 v;
            v.x = acc[i][j + 0] + (B ? B[tx * RN + j + 0] : 0.f);
            v.y = acc[i][j + 1] + (B ? B[tx * RN + j + 1] : 0.f);
            v.z = acc[i][j + 2] + (B ? B[tx * RN + j + 2] : 0.f);
            v.w = acc[i][j + 3] + (B ? B[tx * RN + j + 3] : 0.f);
            *(float4*)(Y + (size_t)gr * HOUT + tx * RN + j) = v;
        }
    }
}

// ---------------- aggregation: out[i] = relu(mean_j yl[csr_j] + yr[i]) ----------------
template <int H>
__global__ void agg_kernel(const float* __restrict__ yl, const float* __restrict__ yr,
                           float* __restrict__ out, int M)
{
    int gw = (blockIdx.x * blockDim.x + threadIdx.x) >> 5;
    int lane = threadIdx.x & 31;
    if (gw >= M) return;
    int beg = g_rowptr[gw];
    int end = g_rowptr[gw + 1];
    float di = g_dinv[gw];

    if (H == 128) {
        float ax = 0.f, ay = 0.f, az = 0.f, aw = 0.f;
        const float* base = yl + lane * 4;
        for (int e = beg; e < end; e++) {
            int s = g_csr[e];
            float4 v = *(const float4*)(base + (size_t)s * 128);
            ax += v.x; ay += v.y; az += v.z; aw += v.w;
        }
        float4 r = *(const float4*)(yr + (size_t)gw * 128 + lane * 4);
        float4 o;
        o.x = fmaxf(ax * di + r.x, 0.f);
        o.y = fmaxf(ay * di + r.y, 0.f);
        o.z = fmaxf(az * di + r.z, 0.f);
        o.w = fmaxf(aw * di + r.w, 0.f);
        *(float4*)(out + (size_t)gw * 128 + lane * 4) = o;
    } else {
        float ax = 0.f, ay = 0.f;
        const float* base = yl + lane * 2;
        for (int e = beg; e < end; e++) {
            int s = g_csr[e];
            float2 v = *(const float2*)(base + (size_t)s * 64);
            ax += v.x; ay += v.y;
        }
        float2 r = *(const float2*)(yr + (size_t)gw * 64 + lane * 2);
        float2 o;
        o.x = fmaxf(ax * di + r.x, 0.f);
        o.y = fmaxf(ay * di + r.y, 0.f);
        *(float2*)(out + (size_t)gw * 64 + lane * 2) = o;
    }
}

// ---------------- final projection: out = h[50000,64] @ w_out[64,4] + b_out ----------------
__global__ void out_kernel(const float* __restrict__ h, const float* __restrict__ wout,
                           const float* __restrict__ bout, float* __restrict__ out)
{
    __shared__ float ws[256];
    __shared__ float bs[4];
    int t = threadIdx.x;
    if (t < 256) ws[t] = wout[t];
    if (t < 4) bs[t] = bout[t];
    __syncthreads();
    int i = blockIdx.x * blockDim.x + t;
    if (i >= NN) return;
    const float* hp = h + (size_t)i * 64;
    float acc[4] = {bs[0], bs[1], bs[2], bs[3]};
#pragma unroll
    for (int k = 0; k < 64; k += 4) {
        float4 v = *(const float4*)(hp + k);
#pragma unroll
        for (int c = 0; c < 4; c++)
            acc[c] += v.x * ws[(k + 0) * 4 + c] + v.y * ws[(k + 1) * 4 + c]
                    + v.z * ws[(k + 2) * 4 + c] + v.w * ws[(k + 3) * 4 + c];
    }
    float4 o = make_float4(acc[0], acc[1], acc[2], acc[3]);
    *(float4*)(out + (size_t)i * 4) = o;
}

// ---------------- launch ----------------
extern "C" void kernel_launch(void* const* d_in, const int* in_sizes, int n_in,
                              void* d_out, int out_size)
{
    (void)in_sizes; (void)n_in; (void)out_size;
    const float* x     = (const float*)d_in[0];
    const int*   ei    = (const int*)d_in[1];
    // d_in[2] = edge_type (unused)
    const float* w_l0  = (const float*)d_in[3];
    const float* w_r0  = (const float*)d_in[4];
    const float* b0    = (const float*)d_in[5];
    const float* w_l1  = (const float*)d_in[6];
    const float* w_r1  = (const float*)d_in[7];
    const float* b1    = (const float*)d_in[8];
    const float* w_l2  = (const float*)d_in[9];
    const float* w_r2  = (const float*)d_in[10];
    const float* b2    = (const float*)d_in[11];
    const float* w_out = (const float*)d_in[12];
    const float* b_out = (const float*)d_in[13];
    float* out = (float*)d_out;

    const int* srcp = ei;
    const int* dstp = ei + NE;

    float *tl, *tr, *h1, *h2;
    cudaGetSymbolAddress((void**)&tl, g_tl);
    cudaGetSymbolAddress((void**)&tr, g_tr);
    cudaGetSymbolAddress((void**)&h1, g_h1);
    cudaGetSymbolAddress((void**)&h2, g_h2);

    // ---- CSR build (once per launch; graph topology is constant across layers) ----
    zero_cnt_kernel<<<(NN + 255) / 256, 256>>>();
    hist_kernel<<<(NE + 255) / 256, 256>>>(dstp);
    scan_kernel<<<1, 1024>>>();
    scatter_kernel<<<(NE + 255) / 256, 256>>>(srcp, dstp);

    dim3 ggrid128((NN + 127) / 128, 2);
    int agg_blocks = (NN + 7) / 8;  // 8 warps/block, warp per node

    // ---- layer 0 ----
    gemm2_kernel<128><<<ggrid128, 256>>>(x, w_l0, w_r0, b0, tl, tr, NN);
    agg_kernel<128><<<agg_blocks, 256>>>(tl, tr, h1, NN);
    // ---- layer 1 ----
    gemm2_kernel<128><<<ggrid128, 256>>>(h1, w_l1, w_r1, b1, tl, tr, NN);
    agg_kernel<128><<<agg_blocks, 256>>>(tl, tr, h2, NN);
    // ---- layer 2 (output width 64; pre-transform halves gather traffic) ----
    gemm2_kernel<64><<<ggrid128, 256>>>(h2, w_l2, w_r2, b2, tl, tr, NN);
    agg_kernel<64><<<agg_blocks, 256>>>(tl, tr, h1, NN);
    // ---- classifier head ----
    out_kernel<<<(NN + 255) / 256, 256>>>(h1, w_out, b_out, out);
}

// round 3
// speedup vs baseline: 1.4073x; 1.4073x over previous
#include <cuda_runtime.h>
#include <cuda_bf16.h>
#include <cuda_fp16.h>
#include <cstdint>
#include <cstddef>

#define NN 50000
#define NE 800000

// ---------------- scratch (static device globals) ----------------
__device__ int   g_cnt[NN];
__device__ int   g_rowptr[NN + 1];
__device__ int   g_wr[NN];
__device__ int   g_csr[NE];
__device__ float g_dinv[NN];
__device__ __nv_bfloat16 g_xhi[(size_t)NN * 128];
__device__ __nv_bfloat16 g_xlo[(size_t)NN * 128];
__device__ __half        g_ylh[(size_t)NN * 128];
__device__ float         g_yrf[(size_t)NN * 128];
__device__ __nv_bfloat16 g_wt[256 * 256];   // weights, [NOUT][256] : k<128 = hi, k>=128 = lo

// ---------------- PTX helpers (base ISA only; no sm_103a features) ----------------
__device__ __forceinline__ uint32_t su32(const void* p) {
    uint32_t a;
    asm("{ .reg .u64 t; cvta.to.shared.u64 t, %1; cvt.u32.u64 %0, t; }" : "=r"(a) : "l"(p));
    return a;
}
__device__ __forceinline__ void ldsm4(uint32_t* r, uint32_t addr) {
    asm volatile("ldmatrix.sync.aligned.m8n8.x4.shared.b16 {%0,%1,%2,%3}, [%4];"
                 : "=r"(r[0]), "=r"(r[1]), "=r"(r[2]), "=r"(r[3]) : "r"(addr));
}
__device__ __forceinline__ void mma16816(float* d, const uint32_t* a, const uint32_t* b) {
    asm volatile(
        "mma.sync.aligned.m16n8k16.row.col.f32.bf16.bf16.f32 "
        "{%0,%1,%2,%3}, {%4,%5,%6,%7}, {%8,%9}, {%0,%1,%2,%3};"
        : "+f"(d[0]), "+f"(d[1]), "+f"(d[2]), "+f"(d[3])
        : "r"(a[0]), "r"(a[1]), "r"(a[2]), "r"(a[3]), "r"(b[0]), "r"(b[1]));
}

// ---------------- CSR build ----------------
__global__ void zero_cnt_kernel() {
    int i = blockIdx.x * blockDim.x + threadIdx.x;
    if (i < NN) g_cnt[i] = 0;
}
__global__ void hist_kernel(const int* __restrict__ dst) {
    int e = blockIdx.x * blockDim.x + threadIdx.x;
    if (e < NE) atomicAdd(&g_cnt[dst[e]], 1);
}
__global__ void scan_kernel() {
    __shared__ int sm[1024];
    int t = threadIdx.x;
    const int CH = 49;
    int base = t * CH;
    int s = 0;
    for (int j = 0; j < CH; j++) { int i = base + j; if (i < NN) s += g_cnt[i]; }
    sm[t] = s;
    __syncthreads();
    for (int off = 1; off < 1024; off <<= 1) {
        int v = (t >= off) ? sm[t - off] : 0;
        __syncthreads();
        sm[t] += v;
        __syncthreads();
    }
    int run = (t == 0) ? 0 : sm[t - 1];
    for (int j = 0; j < CH; j++) {
        int i = base + j;
        if (i < NN) {
            g_rowptr[i] = run; g_wr[i] = run;
            int c = g_cnt[i];
            g_dinv[i] = 1.0f / (float)((c > 1) ? c : 1);
            run += c;
        }
    }
    if (t == 0) g_rowptr[NN] = NE;
}
__global__ void scatter_kernel(const int* __restrict__ src, const int* __restrict__ dst) {
    int e = blockIdx.x * blockDim.x + threadIdx.x;
    if (e < NE) { int p = atomicAdd(&g_wr[dst[e]], 1); g_csr[p] = src[e]; }
}

// ---------------- layer-0 input split fp32 -> bf16 hi/lo ----------------
__global__ void conv0_kernel(const float* __restrict__ x,
                             __nv_bfloat16* __restrict__ xh, __nv_bfloat16* __restrict__ xl) {
    size_t i = (size_t)blockIdx.x * blockDim.x + threadIdx.x;   // float4 index
    if (i >= (size_t)NN * 32) return;
    float4 v = *(const float4*)(x + i * 4);
    __nv_bfloat16 h0 = __float2bfloat16_rn(v.x), h1 = __float2bfloat16_rn(v.y);
    __nv_bfloat16 h2 = __float2bfloat16_rn(v.z), h3 = __float2bfloat16_rn(v.w);
    __nv_bfloat162 a0 = {h0, h1}, a1 = {h2, h3};
    __nv_bfloat162 b0 = {__float2bfloat16_rn(v.x - __bfloat162float(h0)),
                         __float2bfloat16_rn(v.y - __bfloat162float(h1))};
    __nv_bfloat162 b1 = {__float2bfloat16_rn(v.z - __bfloat162float(h2)),
                         __float2bfloat16_rn(v.w - __bfloat162float(h3))};
    uint2 uh, ul;
    uh.x = *(uint32_t*)&a0; uh.y = *(uint32_t*)&a1;
    ul.x = *(uint32_t*)&b0; ul.y = *(uint32_t*)&b1;
    *(uint2*)(xh + i * 4) = uh;
    *(uint2*)(xl + i * 4) = ul;
}

// ---------------- weight prep: Wt[n][k], n over [Wl cols | Wr cols], k<128=hi, k>=128=lo ----------------
__global__ void wprep_kernel(const float* __restrict__ Wl, const float* __restrict__ Wr,
                             int HO, __nv_bfloat16* __restrict__ Wt) {
    int n = blockIdx.x, k = threadIdx.x;    // k in [0,256)
    int kk = k & 127;
    const float* W = (n < HO) ? Wl : Wr;
    int nn = (n < HO) ? n : n - HO;
    float v = W[kk * HO + nn];
    __nv_bfloat16 hi = __float2bfloat16_rn(v);
    __nv_bfloat16 o = (k < 128) ? hi : __float2bfloat16_rn(v - __bfloat162float(hi));
    Wt[n * 256 + k] = o;
}

// ---------------- HMMA GEMM: Y[M, NOUT] = [Xhi|Xlo|Xhi] @ [Whi;Whi;Wlo] ----------------
// block tile 128(M) x 128(N), 8 warps as 4x2, warp tile 32x64.
// smem: A [128][128] bf16 swizzled @0, B [128][128] bf16 swizzled @32768 ([N][K] layout),
// epilogue bounce: fp32 [128][132] reusing the same smem.
__global__ void __launch_bounds__(256)
gemm_hmma(const __nv_bfloat16* __restrict__ xhi, const __nv_bfloat16* __restrict__ xlo,
          const __nv_bfloat16* __restrict__ Wt, const float* __restrict__ bias,
          __half* __restrict__ yl, float* __restrict__ yr, int M, int HO)
{
    extern __shared__ char smem[];
    const uint32_t sAu = su32(smem);
    const uint32_t sBu = sAu + 32768;

    int tid = threadIdx.x;
    int wid = tid >> 5, lane = tid & 31;
    int m0 = blockIdx.x * 128;
    int ny = blockIdx.y;
    int hol = HO - ny * 128; hol = hol < 0 ? 0 : (hol > 128 ? 128 : hol);
    int hor = 128 - hol;

    int wm = (wid & 3) * 32;     // warp M offset
    int wn = (wid >> 2) * 64;    // warp N offset

    float acc[16][4];
#pragma unroll
    for (int i = 0; i < 16; i++)
#pragma unroll
        for (int j = 0; j < 4; j++) acc[i][j] = 0.f;

    // precomputed ldmatrix lane rows
    int rowA0 = wm + (lane & 15);
    int rowA1 = rowA0 + 16;
    int rbB = wn + (lane & 7) + ((lane >> 4) << 3);
    uint32_t aA0 = sAu + rowA0 * 256, aA1 = sAu + rowA1 * 256;
    int xA0 = rowA0 & 7, xA1 = rowA1 & 7;

    // segments: it=0 (Xlo * Whi), it=1 (Xhi * Whi, keep B), it=2 (Xhi * Wlo, keep A)
#pragma unroll 1
    for (int it = 0; it < 3; it++) {
        const __nv_bfloat16* Asrc = (it == 0) ? xlo : xhi;
        int koff = (it == 2) ? 128 : 0;
        __syncthreads();
        if (it < 2) {
            // A tile: 128 rows x 16 uint4-units
#pragma unroll
            for (int l = 0; l < 8; l++) {
                int i = tid + l * 256;
                int row = i >> 4, u = i & 15;
                int m = m0 + row;
                uint4 v = make_uint4(0u, 0u, 0u, 0u);
                if (m < M) v = *(const uint4*)(Asrc + (size_t)m * 128 + u * 8);
                *(uint4*)(smem + row * 256 + ((u ^ (row & 7)) << 4)) = v;
            }
        }
        if (it != 1) {
            // B tile: rows n_loc in [0,128), k in [koff, koff+128)
#pragma unroll
            for (int l = 0; l < 8; l++) {
                int i = tid + l * 256;
                int row = i >> 4, u = i & 15;
                uint4 v = *(const uint4*)(Wt + (size_t)(ny * 128 + row) * 256 + koff + u * 8);
                *(uint4*)(smem + 32768 + row * 256 + ((u ^ (row & 7)) << 4)) = v;
            }
        }
        __syncthreads();

#pragma unroll
        for (int k16 = 0; k16 < 8; k16++) {
            uint32_t a[2][4], b[4][4];
            int ua = (k16 << 1) + (lane >> 4);
            ldsm4(a[0], aA0 + ((ua ^ xA0) << 4));
            ldsm4(a[1], aA1 + ((ua ^ xA1) << 4));
            int ub = (k16 << 1) + ((lane >> 3) & 1);
#pragma unroll
            for (int nj = 0; nj < 4; nj++) {
                int rb = rbB + nj * 16;
                ldsm4(b[nj], sBu + rb * 256 + ((ub ^ (rb & 7)) << 4));
            }
#pragma unroll
            for (int mi = 0; mi < 2; mi++)
#pragma unroll
                for (int nj2 = 0; nj2 < 8; nj2++)
                    mma16816(acc[mi * 8 + nj2], a[mi], &b[nj2 >> 1][(nj2 & 1) * 2]);
        }
    }
    __syncthreads();

    // epilogue: acc -> fp32 smem bounce [128][132]
    float* sf = (float*)smem;
    {
        int r0 = wm + (lane >> 2);
        int c0 = wn + (lane & 3) * 2;
#pragma unroll
        for (int mi = 0; mi < 2; mi++)
#pragma unroll
            for (int nj2 = 0; nj2 < 8; nj2++) {
                float* d = acc[mi * 8 + nj2];
                int r = r0 + mi * 16, c = c0 + nj2 * 8;
                *(float2*)(sf + r * 132 + c) = make_float2(d[0], d[1]);
                *(float2*)(sf + (r + 8) * 132 + c) = make_float2(d[2], d[3]);
            }
    }
    __syncthreads();

    if (hol > 0) {
        // cols [0,hol) -> yl (fp16), global col = local col
        int chunks = hol >> 2;                       // float4 chunks/row: 16 or 32
        int cb = (chunks == 32) ? 5 : 4;
        int total = 128 << cb;
        for (int i = tid; i < total; i += 256) {
            int r2 = i >> cb, cc = i & (chunks - 1);
            int m = m0 + r2;
            if (m < M) {
                float4 v = *(float4*)(sf + r2 * 132 + cc * 4);
                __half2 h0 = __floats2half2_rn(v.x, v.y);
                __half2 h1 = __floats2half2_rn(v.z, v.w);
                uint2 u; u.x = *(uint32_t*)&h0; u.y = *(uint32_t*)&h1;
                *(uint2*)(yl + (size_t)m * HO + cc * 4) = u;
            }
        }
    }
    if (hor > 0) {
        // cols [hol,128) -> yr (fp32) + bias, yr col = local col - hol
        int chunks = hor >> 2;
        int cb = (chunks == 32) ? 5 : 4;
        int total = 128 << cb;
        for (int i = tid; i < total; i += 256) {
            int r2 = i >> cb, cc = i & (chunks - 1);
            int m = m0 + r2;
            if (m < M) {
                float4 v = *(float4*)(sf + r2 * 132 + hol + cc * 4);
                float4 bv = *(const float4*)(bias + cc * 4);
                v.x += bv.x; v.y += bv.y; v.z += bv.z; v.w += bv.w;
                *(float4*)(yr + (size_t)m * HO + cc * 4) = v;
            }
        }
    }
}

// ---------------- aggregation (H=128): relu(mean + yr) -> split bf16 hi/lo ----------------
__global__ void agg128_kernel(const __half* __restrict__ yl, const float* __restrict__ yrv,
                              __nv_bfloat16* __restrict__ xh, __nv_bfloat16* __restrict__ xl, int M)
{
    int gw = (blockIdx.x * blockDim.x + threadIdx.x) >> 5;
    int lane = threadIdx.x & 31;
    if (gw >= M) return;
    int beg = g_rowptr[gw], end = g_rowptr[gw + 1];
    float di = g_dinv[gw];

    float a0 = 0.f, a1 = 0.f, a2 = 0.f, a3 = 0.f;
    const __half* base = yl + lane * 4;
    int e = beg;
    for (; e + 2 <= end; e += 2) {
        int s0 = g_csr[e], s1 = g_csr[e + 1];
        uint2 r0 = *(const uint2*)(base + (size_t)s0 * 128);
        uint2 r1 = *(const uint2*)(base + (size_t)s1 * 128);
        float2 f0 = __half22float2(*(__half2*)&r0.x), f1 = __half22float2(*(__half2*)&r0.y);
        float2 g0 = __half22float2(*(__half2*)&r1.x), g1 = __half22float2(*(__half2*)&r1.y);
        a0 += f0.x + g0.x; a1 += f0.y + g0.y; a2 += f1.x + g1.x; a3 += f1.y + g1.y;
    }
    if (e < end) {
        int s0 = g_csr[e];
        uint2 r0 = *(const uint2*)(base + (size_t)s0 * 128);
        float2 f0 = __half22float2(*(__half2*)&r0.x), f1 = __half22float2(*(__half2*)&r0.y);
        a0 += f0.x; a1 += f0.y; a2 += f1.x; a3 += f1.y;
    }
    float4 r = *(const float4*)(yrv + (size_t)gw * 128 + lane * 4);
    float v0 = fmaxf(a0 * di + r.x, 0.f);
    float v1 = fmaxf(a1 * di + r.y, 0.f);
    float v2 = fmaxf(a2 * di + r.z, 0.f);
    float v3 = fmaxf(a3 * di + r.w, 0.f);

    __nv_bfloat16 h0 = __float2bfloat16_rn(v0), h1 = __float2bfloat16_rn(v1);
    __nv_bfloat16 h2 = __float2bfloat16_rn(v2), h3 = __float2bfloat16_rn(v3);
    __nv_bfloat162 ph0 = {h0, h1}, ph1 = {h2, h3};
    __nv_bfloat162 pl0 = {__float2bfloat16_rn(v0 - __bfloat162float(h0)),
                          __float2bfloat16_rn(v1 - __bfloat162float(h1))};
    __nv_bfloat162 pl1 = {__float2bfloat16_rn(v2 - __bfloat162float(h2)),
                          __float2bfloat16_rn(v3 - __bfloat162float(h3))};
    uint2 uh, ul;
    uh.x = *(uint32_t*)&ph0; uh.y = *(uint32_t*)&ph1;
    ul.x = *(uint32_t*)&pl0; ul.y = *(uint32_t*)&pl1;
    *(uint2*)(xh + (size_t)gw * 128 + lane * 4) = uh;
    *(uint2*)(xl + (size_t)gw * 128 + lane * 4) = ul;
}

// ---------------- aggregation (H=64) fused with classifier head ----------------
__global__ void agg64_head_kernel(const __half* __restrict__ yl, const float* __restrict__ yrv,
                                  const float* __restrict__ wout, const float* __restrict__ bout,
                                  float* __restrict__ out, int M)
{
    __shared__ float ws[256];
    __shared__ float bs[4];
    int t = threadIdx.x;
    ws[t] = wout[t];
    if (t < 4) bs[t] = bout[t];
    __syncthreads();
    int gw = blockIdx.x * 8 + (t >> 5);
    int lane = t & 31;
    if (gw >= M) return;
    int beg = g_rowptr[gw], end = g_rowptr[gw + 1];
    float di = g_dinv[gw];

    float a0 = 0.f, a1 = 0.f;
    const __half* base = yl + lane * 2;
    int e = beg;
    for (; e + 2 <= end; e += 2) {
        int s0 = g_csr[e], s1 = g_csr[e + 1];
        float2 f0 = __half22float2(*(const __half2*)(base + (size_t)s0 * 64));
        float2 f1 = __half22float2(*(const __half2*)(base + (size_t)s1 * 64));
        a0 += f0.x + f1.x; a1 += f0.y + f1.y;
    }
    if (e < end) {
        float2 f0 = __half22float2(*(const __half2*)(base + (size_t)g_csr[e] * 64));
        a0 += f0.x; a1 += f0.y;
    }
    float2 r = *(const float2*)(yrv + (size_t)gw * 64 + lane * 2);
    float v0 = fmaxf(a0 * di + r.x, 0.f);
    float v1 = fmaxf(a1 * di + r.y, 0.f);

    float acc[4];
#pragma unroll
    for (int c = 0; c < 4; c++)
        acc[c] = v0 * ws[(lane * 2) * 4 + c] + v1 * ws[(lane * 2 + 1) * 4 + c];
#pragma unroll
    for (int off = 16; off > 0; off >>= 1) {
#pragma unroll
        for (int c = 0; c < 4; c++)
            acc[c] += __shfl_xor_sync(0xFFFFFFFF, acc[c], off);
    }
    if (lane == 0) {
        float4 o = make_float4(acc[0] + bs[0], acc[1] + bs[1], acc[2] + bs[2], acc[3] + bs[3]);
        *(float4*)(out + (size_t)gw * 4) = o;
    }
}

// ---------------- launch ----------------
extern "C" void kernel_launch(void* const* d_in, const int* in_sizes, int n_in,
                              void* d_out, int out_size)
{
    (void)in_sizes; (void)n_in; (void)out_size;
    const float* x     = (const float*)d_in[0];
    const int*   ei    = (const int*)d_in[1];
    const float* w_l0  = (const float*)d_in[3];
    const float* w_r0  = (const float*)d_in[4];
    const float* b0    = (const float*)d_in[5];
    const float* w_l1  = (const float*)d_in[6];
    const float* w_r1  = (const float*)d_in[7];
    const float* b1    = (const float*)d_in[8];
    const float* w_l2  = (const float*)d_in[9];
    const float* w_r2  = (const float*)d_in[10];
    const float* b2    = (const float*)d_in[11];
    const float* w_out = (const float*)d_in[12];
    const float* b_out = (const float*)d_in[13];
    float* out = (float*)d_out;

    const int* srcp = ei;
    const int* dstp = ei + NE;

    __nv_bfloat16 *xhi, *xlo, *wt;
    __half* ylh;
    float* yrf;
    cudaGetSymbolAddress((void**)&xhi, g_xhi);
    cudaGetSymbolAddress((void**)&xlo, g_xlo);
    cudaGetSymbolAddress((void**)&ylh, g_ylh);
    cudaGetSymbolAddress((void**)&yrf, g_yrf);
    cudaGetSymbolAddress((void**)&wt,  g_wt);

    static int smem_set = 0;
    if (!smem_set) {
        cudaFuncSetAttribute(gemm_hmma, cudaFuncAttributeMaxDynamicSharedMemorySize, 67584);
        smem_set = 1;
    }

    // CSR build
    zero_cnt_kernel<<<(NN + 255) / 256, 256>>>();
    hist_kernel<<<(NE + 255) / 256, 256>>>(dstp);
    scan_kernel<<<1, 1024>>>();
    scatter_kernel<<<(NE + 255) / 256, 256>>>(srcp, dstp);

    // input split
    conv0_kernel<<<(NN * 32 + 255) / 256, 256>>>(x, xhi, xlo);

    int gblk = (NN + 127) / 128;
    int ablk = (NN + 7) / 8;

    // layer 0
    wprep_kernel<<<256, 256>>>(w_l0, w_r0, 128, wt);
    gemm_hmma<<<dim3(gblk, 2), 256, 67584>>>(xhi, xlo, wt, b0, ylh, yrf, NN, 128);
    agg128_kernel<<<ablk, 256>>>(ylh, yrf, xhi, xlo, NN);
    // layer 1
    wprep_kernel<<<256, 256>>>(w_l1, w_r1, 128, wt);
    gemm_hmma<<<dim3(gblk, 2), 256, 67584>>>(xhi, xlo, wt, b1, ylh, yrf, NN, 128);
    agg128_kernel<<<ablk, 256>>>(ylh, yrf, xhi, xlo, NN);
    // layer 2 (HO=64: cols 0..63 -> yl, 64..127 -> yr)
    wprep_kernel<<<128, 256>>>(w_l2, w_r2, 64, wt);
    gemm_hmma<<<dim3(gblk, 1), 256, 67584>>>(xhi, xlo, wt, b2, ylh, yrf, NN, 64);
    // final aggregation + classifier head fused
    agg64_head_kernel<<<ablk, 256>>>(ylh, yrf, w_out, b_out, out, NN);
}

// round 4
// speedup vs baseline: 1.4165x; 1.0066x over previous
#include <cuda_runtime.h>
#include <cuda_bf16.h>
#include <cuda_fp16.h>
#include <cstdint>
#include <cstddef>

#define NN 50000
#define NE 800000

// ---------------- scratch (static device globals) ----------------
__device__ int   g_cnt[NN];
__device__ int   g_rowptr[NN + 1];
__device__ int   g_wr[NN];
__device__ int   g_csr[NE];
__device__ float g_dinv[NN];
__device__ __nv_bfloat16 g_xhi[(size_t)NN * 128];
__device__ __nv_bfloat16 g_xlo[(size_t)NN * 128];
__device__ __half        g_ylh[(size_t)NN * 128];
__device__ float         g_yrf[(size_t)NN * 128];
__device__ __nv_bfloat16 g_wt[3 * 256 * 256];  // 3 layers of [NOUT][256] (k<128 = hi, k>=128 = lo)

// ---------------- PTX helpers (base ISA only) ----------------
__device__ __forceinline__ uint32_t su32(const void* p) {
    uint32_t a;
    asm("{ .reg .u64 t; cvta.to.shared.u64 t, %1; cvt.u32.u64 %0, t; }" : "=r"(a) : "l"(p));
    return a;
}
__device__ __forceinline__ void ldsm4(uint32_t* r, uint32_t addr) {
    asm volatile("ldmatrix.sync.aligned.m8n8.x4.shared.b16 {%0,%1,%2,%3}, [%4];"
                 : "=r"(r[0]), "=r"(r[1]), "=r"(r[2]), "=r"(r[3]) : "r"(addr));
}
__device__ __forceinline__ void mma16816(float* d, const uint32_t* a, const uint32_t* b) {
    asm volatile(
        "mma.sync.aligned.m16n8k16.row.col.f32.bf16.bf16.f32 "
        "{%0,%1,%2,%3}, {%4,%5,%6,%7}, {%8,%9}, {%0,%1,%2,%3};"
        : "+f"(d[0]), "+f"(d[1]), "+f"(d[2]), "+f"(d[3])
        : "r"(a[0]), "r"(a[1]), "r"(a[2]), "r"(a[3]), "r"(b[0]), "r"(b[1]));
}
__device__ __forceinline__ void cpasync16(uint32_t dst, const void* src, uint32_t sz) {
    asm volatile("cp.async.cg.shared.global [%0], [%1], 16, %2;"
                 :: "r"(dst), "l"(src), "r"(sz) : "memory");
}
#define CP_COMMIT() asm volatile("cp.async.commit_group;" ::: "memory")
#define CP_WAIT(n)  asm volatile("cp.async.wait_group %0;" :: "n"(n) : "memory")

// ---------------- CSR build ----------------
__global__ void zero_cnt_kernel() {
    int i = blockIdx.x * blockDim.x + threadIdx.x;
    if (i < NN) g_cnt[i] = 0;
}
__global__ void hist_kernel(const int* __restrict__ dst) {
    int e = blockIdx.x * blockDim.x + threadIdx.x;
    if (e < NE) atomicAdd(&g_cnt[dst[e]], 1);
}
__global__ void scan_kernel() {
    __shared__ int sm[1024];
    int t = threadIdx.x;
    const int CH = 49;
    int base = t * CH;
    int s = 0;
    for (int j = 0; j < CH; j++) { int i = base + j; if (i < NN) s += g_cnt[i]; }
    sm[t] = s;
    __syncthreads();
    for (int off = 1; off < 1024; off <<= 1) {
        int v = (t >= off) ? sm[t - off] : 0;
        __syncthreads();
        sm[t] += v;
        __syncthreads();
    }
    int run = (t == 0) ? 0 : sm[t - 1];
    for (int j = 0; j < CH; j++) {
        int i = base + j;
        if (i < NN) {
            g_rowptr[i] = run; g_wr[i] = run;
            int c = g_cnt[i];
            g_dinv[i] = 1.0f / (float)((c > 1) ? c : 1);
            run += c;
        }
    }
    if (t == 0) g_rowptr[NN] = NE;
}
__global__ void scatter_kernel(const int* __restrict__ src, const int* __restrict__ dst) {
    int e = blockIdx.x * blockDim.x + threadIdx.x;
    if (e < NE) { int p = atomicAdd(&g_wr[dst[e]], 1); g_csr[p] = src[e]; }
}

// ---------------- layer-0 input split fp32 -> bf16 hi/lo ----------------
__global__ void conv0_kernel(const float* __restrict__ x,
                             __nv_bfloat16* __restrict__ xh, __nv_bfloat16* __restrict__ xl) {
    size_t i = (size_t)blockIdx.x * blockDim.x + threadIdx.x;
    if (i >= (size_t)NN * 32) return;
    float4 v = *(const float4*)(x + i * 4);
    __nv_bfloat16 h0 = __float2bfloat16_rn(v.x), h1 = __float2bfloat16_rn(v.y);
    __nv_bfloat16 h2 = __float2bfloat16_rn(v.z), h3 = __float2bfloat16_rn(v.w);
    __nv_bfloat162 a0 = {h0, h1}, a1 = {h2, h3};
    __nv_bfloat162 b0 = {__float2bfloat16_rn(v.x - __bfloat162float(h0)),
                         __float2bfloat16_rn(v.y - __bfloat162float(h1))};
    __nv_bfloat162 b1 = {__float2bfloat16_rn(v.z - __bfloat162float(h2)),
                         __float2bfloat16_rn(v.w - __bfloat162float(h3))};
    uint2 uh, ul;
    uh.x = *(uint32_t*)&a0; uh.y = *(uint32_t*)&a1;
    ul.x = *(uint32_t*)&b0; ul.y = *(uint32_t*)&b1;
    *(uint2*)(xh + i * 4) = uh;
    *(uint2*)(xl + i * 4) = ul;
}

// ---------------- weight prep: Wt[n][k], n over [Wl | Wr], k<128=hi, k>=128=lo ----------------
__global__ void wprep_kernel(const float* __restrict__ Wl, const float* __restrict__ Wr,
                             int HO, __nv_bfloat16* __restrict__ Wt) {
    int n = blockIdx.x, k = threadIdx.x;
    int kk = k & 127;
    const float* W = (n < HO) ? Wl : Wr;
    int nn = (n < HO) ? n : n - HO;
    float v = W[kk * HO + nn];
    __nv_bfloat16 hi = __float2bfloat16_rn(v);
    __nv_bfloat16 o = (k < 128) ? hi : __float2bfloat16_rn(v - __bfloat162float(hi));
    Wt[n * 256 + k] = o;
}

// ---------------- segment compute: 8 k16 steps, reg-double-buffered ldsm -> mma ----------------
struct Frag { uint32_t a0[4], a1[4], b[4][4]; };

__device__ __forceinline__ void seg_load(Frag& f, int k16,
                                         uint32_t aA0, uint32_t aA1, int xA0, int xA1,
                                         uint32_t bB, int rbB, int lane) {
    int ua = (k16 << 1) + (lane >> 4);
    ldsm4(f.a0, aA0 + ((ua ^ xA0) << 4));
    ldsm4(f.a1, aA1 + ((ua ^ xA1) << 4));
    int ub = (k16 << 1) + ((lane >> 3) & 1);
#pragma unroll
    for (int nj = 0; nj < 4; nj++) {
        int rb = rbB + nj * 16;
        ldsm4(f.b[nj], bB + rb * 256 + ((ub ^ (rb & 7)) << 4));
    }
}
__device__ __forceinline__ void seg_mma(const Frag& f, float acc[16][4]) {
#pragma unroll
    for (int mi = 0; mi < 2; mi++) {
        const uint32_t* a = mi ? f.a1 : f.a0;
#pragma unroll
        for (int nj2 = 0; nj2 < 8; nj2++)
            mma16816(acc[mi * 8 + nj2], a, &f.b[nj2 >> 1][(nj2 & 1) * 2]);
    }
}

// ---------------- HMMA GEMM with full cp.async prefetch ----------------
// smem: A0(xlo)@0  A1(xhi)@32K  B0(Whi)@64K  B1(Wlo)@96K ; epilogue fp32 bounce reuses [0,67.6K)
__global__ void __launch_bounds__(256)
gemm_hmma(const __nv_bfloat16* __restrict__ xhi, const __nv_bfloat16* __restrict__ xlo,
          const __nv_bfloat16* __restrict__ Wt, const float* __restrict__ bias,
          __half* __restrict__ yl, float* __restrict__ yr, int M, int HO)
{
    extern __shared__ char smem[];
    const uint32_t sb = su32(smem);

    int tid = threadIdx.x;
    int wid = tid >> 5, lane = tid & 31;
    int m0 = blockIdx.x * 128;
    int ny = blockIdx.y;
    int hol = HO - ny * 128; hol = hol < 0 ? 0 : (hol > 128 ? 128 : hol);
    int hor = 128 - hol;

    int wm = (wid & 3) * 32;
    int wn = (wid >> 2) * 64;

    // ---- cp.async prefetch all four tiles ----
    {
        int row = tid >> 1;                        // 0..127 (2 threads per row)
        int uh = (tid & 1) * 8;                    // uint4-unit base: 0 or 8
        int m = m0 + row;
        uint32_t szA = (m < M) ? 16u : 0u;
        const __nv_bfloat16* aLo = xlo + (size_t)m * 128;
        const __nv_bfloat16* aHi = xhi + (size_t)m * 128;
        const __nv_bfloat16* wRow = Wt + (size_t)(ny * 128 + row) * 256;
        uint32_t dA = sb + row * 256;
        uint32_t dB0 = sb + 65536 + row * 256;
#pragma unroll
        for (int j = 0; j < 8; j++) {
            int u = uh + j;
            uint32_t so = (uint32_t)((u ^ (row & 7)) << 4);
            cpasync16(dA + so, aLo + u * 8, szA);                    // A0 = xlo
            cpasync16(dB0 + so, wRow + u * 8, 16u);                  // B0 = Whi
        }
        CP_COMMIT();
#pragma unroll
        for (int j = 0; j < 8; j++) {
            int u = uh + j;
            uint32_t so = (uint32_t)((u ^ (row & 7)) << 4);
            cpasync16(dA + 32768 + so, aHi + u * 8, szA);            // A1 = xhi
            cpasync16(dB0 + 32768 + so, wRow + 128 + u * 8, 16u);    // B1 = Wlo
        }
        CP_COMMIT();
    }

    float acc[16][4];
#pragma unroll
    for (int i = 0; i < 16; i++)
#pragma unroll
        for (int j = 0; j < 4; j++) acc[i][j] = 0.f;

    int rowA0 = wm + (lane & 15);
    int rowA1 = rowA0 + 16;
    int rbB = wn + (lane & 7) + ((lane >> 4) << 3);
    int xA0 = rowA0 & 7, xA1 = rowA1 & 7;

    Frag f[2];

    // ---- segment 0: xlo * Whi ----
    CP_WAIT(1);
    __syncthreads();
    {
        uint32_t aA0 = sb + rowA0 * 256, aA1 = sb + rowA1 * 256, bB = sb + 65536;
        seg_load(f[0], 0, aA0, aA1, xA0, xA1, bB, rbB, lane);
#pragma unroll
        for (int k16 = 0; k16 < 8; k16++) {
            if (k16 < 7) seg_load(f[(k16 + 1) & 1], k16 + 1, aA0, aA1, xA0, xA1, bB, rbB, lane);
            seg_mma(f[k16 & 1], acc);
        }
    }
    // ---- segments 1,2: xhi * Whi, xhi * Wlo ----
    CP_WAIT(0);
    __syncthreads();
    {
        uint32_t aA0 = sb + 32768 + rowA0 * 256, aA1 = sb + 32768 + rowA1 * 256;
#pragma unroll 1
        for (int it = 0; it < 2; it++) {
            uint32_t bB = sb + 65536 + it * 32768;
            seg_load(f[0], 0, aA0, aA1, xA0, xA1, bB, rbB, lane);
#pragma unroll
            for (int k16 = 0; k16 < 8; k16++) {
                if (k16 < 7) seg_load(f[(k16 + 1) & 1], k16 + 1, aA0, aA1, xA0, xA1, bB, rbB, lane);
                seg_mma(f[k16 & 1], acc);
            }
        }
    }
    __syncthreads();

    // ---- epilogue: fp32 smem bounce [128][132] ----
    float* sf = (float*)smem;
    {
        int r0 = wm + (lane >> 2);
        int c0 = wn + (lane & 3) * 2;
#pragma unroll
        for (int mi = 0; mi < 2; mi++)
#pragma unroll
            for (int nj2 = 0; nj2 < 8; nj2++) {
                float* d = acc[mi * 8 + nj2];
                int r = r0 + mi * 16, c = c0 + nj2 * 8;
                *(float2*)(sf + r * 132 + c) = make_float2(d[0], d[1]);
                *(float2*)(sf + (r + 8) * 132 + c) = make_float2(d[2], d[3]);
            }
    }
    __syncthreads();

    if (hol > 0) {
        int chunks = hol >> 2;
        int cb = (chunks == 32) ? 5 : 4;
        int total = 128 << cb;
        for (int i = tid; i < total; i += 256) {
            int r2 = i >> cb, cc = i & (chunks - 1);
            int m = m0 + r2;
            if (m < M) {
                float4 v = *(float4*)(sf + r2 * 132 + cc * 4);
                __half2 h0 = __floats2half2_rn(v.x, v.y);
                __half2 h1 = __floats2half2_rn(v.z, v.w);
                uint2 u; u.x = *(uint32_t*)&h0; u.y = *(uint32_t*)&h1;
                *(uint2*)(yl + (size_t)m * HO + cc * 4) = u;
            }
        }
    }
    if (hor > 0) {
        int chunks = hor >> 2;
        int cb = (chunks == 32) ? 5 : 4;
        int total = 128 << cb;
        for (int i = tid; i < total; i += 256) {
            int r2 = i >> cb, cc = i & (chunks - 1);
            int m = m0 + r2;
            if (m < M) {
                float4 v = *(float4*)(sf + r2 * 132 + hol + cc * 4);
                float4 bv = *(const float4*)(bias + cc * 4);
                v.x += bv.x; v.y += bv.y; v.z += bv.z; v.w += bv.w;
                *(float4*)(yr + (size_t)m * HO + cc * 4) = v;
            }
        }
    }
}

// ---------------- aggregation (H=128): relu(mean + yr) -> split bf16 hi/lo ----------------
__global__ void agg128_kernel(const __half* __restrict__ yl, const float* __restrict__ yrv,
                              __nv_bfloat16* __restrict__ xh, __nv_bfloat16* __restrict__ xl, int M)
{
    int gw = (blockIdx.x * blockDim.x + threadIdx.x) >> 5;
    int lane = threadIdx.x & 31;
    if (gw >= M) return;
    int beg = g_rowptr[gw], end = g_rowptr[gw + 1];
    float di = g_dinv[gw];

    float a0 = 0.f, a1 = 0.f, a2 = 0.f, a3 = 0.f;
    const __half* base = yl + lane * 4;
    int e = beg;
    for (; e + 2 <= end; e += 2) {
        int s0 = g_csr[e], s1 = g_csr[e + 1];
        uint2 r0 = *(const uint2*)(base + (size_t)s0 * 128);
        uint2 r1 = *(const uint2*)(base + (size_t)s1 * 128);
        float2 f0 = __half22float2(*(__half2*)&r0.x), f1 = __half22float2(*(__half2*)&r0.y);
        float2 g0 = __half22float2(*(__half2*)&r1.x), g1 = __half22float2(*(__half2*)&r1.y);
        a0 += f0.x + g0.x; a1 += f0.y + g0.y; a2 += f1.x + g1.x; a3 += f1.y + g1.y;
    }
    if (e < end) {
        int s0 = g_csr[e];
        uint2 r0 = *(const uint2*)(base + (size_t)s0 * 128);
        float2 f0 = __half22float2(*(__half2*)&r0.x), f1 = __half22float2(*(__half2*)&r0.y);
        a0 += f0.x; a1 += f0.y; a2 += f1.x; a3 += f1.y;
    }
    float4 r = *(const float4*)(yrv + (size_t)gw * 128 + lane * 4);
    float v0 = fmaxf(a0 * di + r.x, 0.f);
    float v1 = fmaxf(a1 * di + r.y, 0.f);
    float v2 = fmaxf(a2 * di + r.z, 0.f);
    float v3 = fmaxf(a3 * di + r.w, 0.f);

    __nv_bfloat16 h0 = __float2bfloat16_rn(v0), h1 = __float2bfloat16_rn(v1);
    __nv_bfloat16 h2 = __float2bfloat16_rn(v2), h3 = __float2bfloat16_rn(v3);
    __nv_bfloat162 ph0 = {h0, h1}, ph1 = {h2, h3};
    __nv_bfloat162 pl0 = {__float2bfloat16_rn(v0 - __bfloat162float(h0)),
                          __float2bfloat16_rn(v1 - __bfloat162float(h1))};
    __nv_bfloat162 pl1 = {__float2bfloat16_rn(v2 - __bfloat162float(h2)),
                          __float2bfloat16_rn(v3 - __bfloat162float(h3))};
    uint2 uh, ul;
    uh.x = *(uint32_t*)&ph0; uh.y = *(uint32_t*)&ph1;
    ul.x = *(uint32_t*)&pl0; ul.y = *(uint32_t*)&pl1;
    *(uint2*)(xh + (size_t)gw * 128 + lane * 4) = uh;
    *(uint2*)(xl + (size_t)gw * 128 + lane * 4) = ul;
}

// ---------------- aggregation (H=64) fused with classifier head ----------------
__global__ void agg64_head_kernel(const __half* __restrict__ yl, const float* __restrict__ yrv,
                                  const float* __restrict__ wout, const float* __restrict__ bout,
                                  float* __restrict__ out, int M)
{
    __shared__ float ws[256];
    __shared__ float bs[4];
    int t = threadIdx.x;
    ws[t] = wout[t];
    if (t < 4) bs[t] = bout[t];
    __syncthreads();
    int gw = blockIdx.x * 8 + (t >> 5);
    int lane = t & 31;
    if (gw >= M) return;
    int beg = g_rowptr[gw], end = g_rowptr[gw + 1];
    float di = g_dinv[gw];

    float a0 = 0.f, a1 = 0.f;
    const __half* base = yl + lane * 2;
    int e = beg;
    for (; e + 2 <= end; e += 2) {
        int s0 = g_csr[e], s1 = g_csr[e + 1];
        float2 f0 = __half22float2(*(const __half2*)(base + (size_t)s0 * 64));
        float2 f1 = __half22float2(*(const __half2*)(base + (size_t)s1 * 64));
        a0 += f0.x + f1.x; a1 += f0.y + f1.y;
    }
    if (e < end) {
        float2 f0 = __half22float2(*(const __half2*)(base + (size_t)g_csr[e] * 64));
        a0 += f0.x; a1 += f0.y;
    }
    float2 r = *(const float2*)(yrv + (size_t)gw * 64 + lane * 2);
    float v0 = fmaxf(a0 * di + r.x, 0.f);
    float v1 = fmaxf(a1 * di + r.y, 0.f);

    float acc[4];
#pragma unroll
    for (int c = 0; c < 4; c++)
        acc[c] = v0 * ws[(lane * 2) * 4 + c] + v1 * ws[(lane * 2 + 1) * 4 + c];
#pragma unroll
    for (int off = 16; off > 0; off >>= 1) {
#pragma unroll
        for (int c = 0; c < 4; c++)
            acc[c] += __shfl_xor_sync(0xFFFFFFFF, acc[c], off);
    }
    if (lane == 0) {
        float4 o = make_float4(acc[0] + bs[0], acc[1] + bs[1], acc[2] + bs[2], acc[3] + bs[3]);
        *(float4*)(out + (size_t)gw * 4) = o;
    }
}

// ---------------- launch ----------------
extern "C" void kernel_launch(void* const* d_in, const int* in_sizes, int n_in,
                              void* d_out, int out_size)
{
    (void)in_sizes; (void)n_in; (void)out_size;
    const float* x     = (const float*)d_in[0];
    const int*   ei    = (const int*)d_in[1];
    const float* w_l0  = (const float*)d_in[3];
    const float* w_r0  = (const float*)d_in[4];
    const float* b0    = (const float*)d_in[5];
    const float* w_l1  = (const float*)d_in[6];
    const float* w_r1  = (const float*)d_in[7];
    const float* b1    = (const float*)d_in[8];
    const float* w_l2  = (const float*)d_in[9];
    const float* w_r2  = (const float*)d_in[10];
    const float* b2    = (const float*)d_in[11];
    const float* w_out = (const float*)d_in[12];
    const float* b_out = (const float*)d_in[13];
    float* out = (float*)d_out;

    const int* srcp = ei;
    const int* dstp = ei + NE;

    __nv_bfloat16 *xhi, *xlo, *wt;
    __half* ylh;
    float* yrf;
    cudaGetSymbolAddress((void**)&xhi, g_xhi);
    cudaGetSymbolAddress((void**)&xlo, g_xlo);
    cudaGetSymbolAddress((void**)&ylh, g_ylh);
    cudaGetSymbolAddress((void**)&yrf, g_yrf);
    cudaGetSymbolAddress((void**)&wt,  g_wt);

    static cudaStream_t s2 = nullptr;
    static cudaEvent_t evFork = nullptr, evJoin = nullptr;
    if (!s2) {
        cudaStreamCreateWithFlags(&s2, cudaStreamNonBlocking);
        cudaEventCreateWithFlags(&evFork, cudaEventDisableTiming);
        cudaEventCreateWithFlags(&evJoin, cudaEventDisableTiming);
        cudaFuncSetAttribute(gemm_hmma, cudaFuncAttributeMaxDynamicSharedMemorySize, 131072);
    }

    // ---- fork: CSR build on side stream ----
    cudaEventRecord(evFork, 0);
    cudaStreamWaitEvent(s2, evFork, 0);
    zero_cnt_kernel<<<(NN + 255) / 256, 256, 0, s2>>>();
    hist_kernel<<<(NE + 255) / 256, 256, 0, s2>>>(dstp);
    scan_kernel<<<1, 1024, 0, s2>>>();
    scatter_kernel<<<(NE + 255) / 256, 256, 0, s2>>>(srcp, dstp);
    cudaEventRecord(evJoin, s2);

    // ---- main stream: input split + all weight preps + layer-0 GEMM ----
    conv0_kernel<<<(NN * 32 + 255) / 256, 256>>>(x, xhi, xlo);
    wprep_kernel<<<256, 256>>>(w_l0, w_r0, 128, wt);
    wprep_kernel<<<256, 256>>>(w_l1, w_r1, 128, wt + 65536);
    wprep_kernel<<<128, 256>>>(w_l2, w_r2, 64, wt + 131072);

    int gblk = (NN + 127) / 128;
    int ablk = (NN + 7) / 8;

    gemm_hmma<<<dim3(gblk, 2), 256, 131072>>>(xhi, xlo, wt, b0, ylh, yrf, NN, 128);

    // ---- join: aggregation needs CSR ----
    cudaStreamWaitEvent(0, evJoin, 0);
    agg128_kernel<<<ablk, 256>>>(ylh, yrf, xhi, xlo, NN);
    // layer 1
    gemm_hmma<<<dim3(gblk, 2), 256, 131072>>>(xhi, xlo, wt + 65536, b1, ylh, yrf, NN, 128);
    agg128_kernel<<<ablk, 256>>>(ylh, yrf, xhi, xlo, NN);
    // layer 2 (HO=64: cols 0..63 -> yl, 64..127 -> yr)
    gemm_hmma<<<dim3(gblk, 1), 256, 131072>>>(xhi, xlo, wt + 131072, b2, ylh, yrf, NN, 64);
    // final aggregation + classifier head fused
    agg64_head_kernel<<<ablk, 256>>>(ylh, yrf, w_out, b_out, out, NN);
}

// round 5
// speedup vs baseline: 1.4205x; 1.0028x over previous
#include <cuda_runtime.h>
#include <cuda_bf16.h>
#include <cuda_fp16.h>
#include <cstdint>
#include <cstddef>

#define NN 50000
#define NE 800000

// ---------------- scratch (static device globals) ----------------
__device__ int   g_cnt[NN];
__device__ int   g_rowptr[NN + 1];
__device__ int   g_wr[NN];
__device__ int   g_csr[NE];
__device__ float g_dinv[NN];
__device__ __nv_bfloat16 g_xhi[(size_t)NN * 128];
__device__ __nv_bfloat16 g_xlo[(size_t)NN * 128];
__device__ __half        g_ylh[(size_t)NN * 128];
__device__ float         g_yrf[(size_t)NN * 128];
__device__ __nv_bfloat16 g_wt[3 * 256 * 256];  // 3 layers of [NOUT][256] (k<128 = hi, k>=128 = lo)

// ---------------- PTX helpers (base ISA only) ----------------
__device__ __forceinline__ uint32_t su32(const void* p) {
    uint32_t a;
    asm("{ .reg .u64 t; cvta.to.shared.u64 t, %1; cvt.u32.u64 %0, t; }" : "=r"(a) : "l"(p));
    return a;
}
__device__ __forceinline__ void ldsm4(uint32_t* r, uint32_t addr) {
    asm volatile("ldmatrix.sync.aligned.m8n8.x4.shared.b16 {%0,%1,%2,%3}, [%4];"
                 : "=r"(r[0]), "=r"(r[1]), "=r"(r[2]), "=r"(r[3]) : "r"(addr));
}
__device__ __forceinline__ void mma16816(float* d, const uint32_t* a, const uint32_t* b) {
    asm volatile(
        "mma.sync.aligned.m16n8k16.row.col.f32.bf16.bf16.f32 "
        "{%0,%1,%2,%3}, {%4,%5,%6,%7}, {%8,%9}, {%0,%1,%2,%3};"
        : "+f"(d[0]), "+f"(d[1]), "+f"(d[2]), "+f"(d[3])
        : "r"(a[0]), "r"(a[1]), "r"(a[2]), "r"(a[3]), "r"(b[0]), "r"(b[1]));
}
__device__ __forceinline__ void cpasync16(uint32_t dst, const void* src, uint32_t sz) {
    asm volatile("cp.async.cg.shared.global [%0], [%1], 16, %2;"
                 :: "r"(dst), "l"(src), "r"(sz) : "memory");
}
#define CP_COMMIT() asm volatile("cp.async.commit_group;" ::: "memory")
#define CP_WAIT(n)  asm volatile("cp.async.wait_group %0;" :: "n"(n) : "memory")

// ---------------- CSR build ----------------
__global__ void zero_cnt_kernel() {
    int i = blockIdx.x * blockDim.x + threadIdx.x;
    if (i < NN) g_cnt[i] = 0;
}
__global__ void hist_kernel(const int* __restrict__ dst) {
    int e = blockIdx.x * blockDim.x + threadIdx.x;
    if (e < NE) atomicAdd(&g_cnt[dst[e]], 1);
}
__global__ void scan_kernel() {
    __shared__ int sm[1024];
    int t = threadIdx.x;
    const int CH = 49;
    int base = t * CH;
    int s = 0;
    for (int j = 0; j < CH; j++) { int i = base + j; if (i < NN) s += g_cnt[i]; }
    sm[t] = s;
    __syncthreads();
    for (int off = 1; off < 1024; off <<= 1) {
        int v = (t >= off) ? sm[t - off] : 0;
        __syncthreads();
        sm[t] += v;
        __syncthreads();
    }
    int run = (t == 0) ? 0 : sm[t - 1];
    for (int j = 0; j < CH; j++) {
        int i = base + j;
        if (i < NN) {
            g_rowptr[i] = run; g_wr[i] = run;
            int c = g_cnt[i];
            g_dinv[i] = 1.0f / (float)((c > 1) ? c : 1);
            run += c;
        }
    }
    if (t == 0) g_rowptr[NN] = NE;
}
__global__ void scatter_kernel(const int* __restrict__ src, const int* __restrict__ dst) {
    int e = blockIdx.x * blockDim.x + threadIdx.x;
    if (e < NE) { int p = atomicAdd(&g_wr[dst[e]], 1); g_csr[p] = src[e]; }
}

// ---------------- layer-0 input split fp32 -> bf16 hi/lo ----------------
__global__ void conv0_kernel(const float* __restrict__ x,
                             __nv_bfloat16* __restrict__ xh, __nv_bfloat16* __restrict__ xl) {
    size_t i = (size_t)blockIdx.x * blockDim.x + threadIdx.x;
    if (i >= (size_t)NN * 32) return;
    float4 v = *(const float4*)(x + i * 4);
    __nv_bfloat16 h0 = __float2bfloat16_rn(v.x), h1 = __float2bfloat16_rn(v.y);
    __nv_bfloat16 h2 = __float2bfloat16_rn(v.z), h3 = __float2bfloat16_rn(v.w);
    __nv_bfloat162 a0 = {h0, h1}, a1 = {h2, h3};
    __nv_bfloat162 b0 = {__float2bfloat16_rn(v.x - __bfloat162float(h0)),
                         __float2bfloat16_rn(v.y - __bfloat162float(h1))};
    __nv_bfloat162 b1 = {__float2bfloat16_rn(v.z - __bfloat162float(h2)),
                         __float2bfloat16_rn(v.w - __bfloat162float(h3))};
    uint2 uh, ul;
    uh.x = *(uint32_t*)&a0; uh.y = *(uint32_t*)&a1;
    ul.x = *(uint32_t*)&b0; ul.y = *(uint32_t*)&b1;
    *(uint2*)(xh + i * 4) = uh;
    *(uint2*)(xl + i * 4) = ul;
}

// ---------------- weight prep: Wt[n][k], n over [Wl | Wr], k<128=hi, k>=128=lo ----------------
__global__ void wprep_kernel(const float* __restrict__ Wl, const float* __restrict__ Wr,
                             int HO, __nv_bfloat16* __restrict__ Wt) {
    int n = blockIdx.x, k = threadIdx.x;
    int kk = k & 127;
    const float* W = (n < HO) ? Wl : Wr;
    int nn = (n < HO) ? n : n - HO;
    float v = W[kk * HO + nn];
    __nv_bfloat16 hi = __float2bfloat16_rn(v);
    __nv_bfloat16 o = (k < 128) ? hi : __float2bfloat16_rn(v - __bfloat162float(hi));
    Wt[n * 256 + k] = o;
}

// ---------------- fragment helpers ----------------
struct Frag { uint32_t a0[4], a1[4], b[4][4]; };

__device__ __forceinline__ void seg_load(Frag& f, int k16,
                                         uint32_t aA0, uint32_t aA1, int xA0, int xA1,
                                         uint32_t bB, int rbB, int lane) {
    int ua = (k16 << 1) + (lane >> 4);
    ldsm4(f.a0, aA0 + ((ua ^ xA0) << 4));
    ldsm4(f.a1, aA1 + ((ua ^ xA1) << 4));
    int ub = (k16 << 1) + ((lane >> 3) & 1);
#pragma unroll
    for (int nj = 0; nj < 4; nj++) {
        int rb = rbB + nj * 16;
        ldsm4(f.b[nj], bB + rb * 256 + ((ub ^ (rb & 7)) << 4));
    }
}
__device__ __forceinline__ void seg_mma(const Frag& f, float acc[16][4]) {
#pragma unroll
    for (int mi = 0; mi < 2; mi++) {
        const uint32_t* a = mi ? f.a1 : f.a0;
#pragma unroll
        for (int nj2 = 0; nj2 < 8; nj2++)
            mma16816(acc[mi * 8 + nj2], a, &f.b[nj2 >> 1][(nj2 & 1) * 2]);
    }
}

// ---------------- persistent HMMA GEMM: weights resident, A double-buffered ----------------
// smem: B0(Whi)@0 32K | B1(Wlo)@32K | Abuf0 (xlo@64K, xhi@96K) | Abuf1 (xlo@128K, xhi@160K) = 192K
__global__ void __launch_bounds__(256)
gemm_pers(const __nv_bfloat16* __restrict__ xhi, const __nv_bfloat16* __restrict__ xlo,
          const __nv_bfloat16* __restrict__ Wt, const float* __restrict__ bias,
          __half* __restrict__ yl, float* __restrict__ yr, int M, int HO)
{
    extern __shared__ char smem[];
    const uint32_t sb = su32(smem);

    int tid = threadIdx.x;
    int wid = tid >> 5, lane = tid & 31;
    int ny = blockIdx.y;
    int hol = HO - ny * 128; hol = hol < 0 ? 0 : (hol > 128 ? 128 : hol);

    int wm = (wid & 3) * 32;
    int wn = (wid >> 2) * 64;

    int row = tid >> 1;              // 0..127, 2 threads per row for loads
    int uh = (tid & 1) * 8;          // uint4 unit base 0/8
    uint32_t soff[8];
#pragma unroll
    for (int j = 0; j < 8; j++) soff[j] = (uint32_t)(((uh + j) ^ (row & 7)) << 4);

    // ---- load resident weights (both halves) ----
    {
        const __nv_bfloat16* wRow = Wt + (size_t)(ny * 128 + row) * 256;
        uint32_t d0 = sb + row * 256, d1 = sb + 32768 + row * 256;
#pragma unroll
        for (int j = 0; j < 8; j++) {
            cpasync16(d0 + soff[j], wRow + (uh + j) * 8, 16u);
            cpasync16(d1 + soff[j], wRow + 128 + (uh + j) * 8, 16u);
        }
    }
    int nt = (M + 127) >> 7;
    int step = gridDim.x;

    // ---- prefetch first tile into buf0 ----
    {
        int t0 = blockIdx.x;
        int m = t0 * 128 + row;
        uint32_t sz = (m < M) ? 16u : 0u;
        const __nv_bfloat16* aL = xlo + (size_t)m * 128;
        const __nv_bfloat16* aH = xhi + (size_t)m * 128;
        uint32_t dL = sb + 65536 + row * 256, dH = dL + 32768;
#pragma unroll
        for (int j = 0; j < 8; j++) {
            cpasync16(dL + soff[j], aL + (uh + j) * 8, sz);
            cpasync16(dH + soff[j], aH + (uh + j) * 8, sz);
        }
    }
    CP_COMMIT();   // G0 = B + A(tile0)

    int rowA0 = wm + (lane & 15);
    int rowA1 = rowA0 + 16;
    int rbB = wn + (lane & 7) + ((lane >> 4) << 3);
    int xA0 = rowA0 & 7, xA1 = rowA1 & 7;
    int r_lane = lane >> 2;
    int c_lane = (lane & 3) * 2;
    bool isl = (wn < hol);
    int cb_yr = wn - hol;

    int p = 0;
    for (int t = blockIdx.x; t < nt; t += step, p ^= 1) {
        // prefetch next tile into buf p^1
        int tn = t + step;
        if (tn < nt) {
            int m = tn * 128 + row;
            uint32_t sz = (m < M) ? 16u : 0u;
            const __nv_bfloat16* aL = xlo + (size_t)m * 128;
            const __nv_bfloat16* aH = xhi + (size_t)m * 128;
            uint32_t dL = sb + 65536 + (p ^ 1) * 65536 + row * 256, dH = dL + 32768;
#pragma unroll
            for (int j = 0; j < 8; j++) {
                cpasync16(dL + soff[j], aL + (uh + j) * 8, sz);
                cpasync16(dH + soff[j], aH + (uh + j) * 8, sz);
            }
        }
        CP_COMMIT();
        CP_WAIT(1);           // current tile (and B) resident; newest group in flight
        __syncthreads();

        float acc[16][4];
#pragma unroll
        for (int i = 0; i < 16; i++)
#pragma unroll
            for (int j = 0; j < 4; j++) acc[i][j] = 0.f;

        uint32_t ab = sb + 65536 + p * 65536;
        uint32_t segA[3] = {ab, ab + 32768u, ab + 32768u};        // xlo, xhi, xhi
        uint32_t segB[3] = {sb, sb, sb + 32768u};                  // Whi, Whi, Wlo

        Frag f[2];
#pragma unroll 1
        for (int it = 0; it < 3; it++) {
            uint32_t aA0 = segA[it] + rowA0 * 256, aA1 = segA[it] + rowA1 * 256;
            uint32_t bB = segB[it];
            seg_load(f[0], 0, aA0, aA1, xA0, xA1, bB, rbB, lane);
#pragma unroll
            for (int k16 = 0; k16 < 8; k16++) {
                if (k16 < 7) seg_load(f[(k16 + 1) & 1], k16 + 1, aA0, aA1, xA0, xA1, bB, rbB, lane);
                seg_mma(f[k16 & 1], acc);
            }
        }

        // ---- epilogue: direct STG from fragments (quad-coalesced) ----
        int m0 = t * 128;
        if (isl) {
#pragma unroll
            for (int mi = 0; mi < 2; mi++) {
                int mb = m0 + wm + mi * 16 + r_lane;
#pragma unroll
                for (int nj2 = 0; nj2 < 8; nj2++) {
                    float* d = acc[mi * 8 + nj2];
                    int col = wn + nj2 * 8 + c_lane;
                    __half2 h01 = __floats2half2_rn(d[0], d[1]);
                    __half2 h23 = __floats2half2_rn(d[2], d[3]);
                    if (mb < M)     *(__half2*)(yl + (size_t)mb * HO + col) = h01;
                    if (mb + 8 < M) *(__half2*)(yl + (size_t)(mb + 8) * HO + col) = h23;
                }
            }
        } else {
#pragma unroll
            for (int mi = 0; mi < 2; mi++) {
                int mb = m0 + wm + mi * 16 + r_lane;
#pragma unroll
                for (int nj2 = 0; nj2 < 8; nj2++) {
                    float* d = acc[mi * 8 + nj2];
                    int col = cb_yr + nj2 * 8 + c_lane;
                    float2 bv = *(const float2*)(bias + col);
                    float2 v01 = make_float2(d[0] + bv.x, d[1] + bv.y);
                    float2 v23 = make_float2(d[2] + bv.x, d[3] + bv.y);
                    if (mb < M)     *(float2*)(yr + (size_t)mb * HO + col) = v01;
                    if (mb + 8 < M) *(float2*)(yr + (size_t)(mb + 8) * HO + col) = v23;
                }
            }
        }
        __syncthreads();   // all warps done with buf p before it is overwritten next iter
    }
}

// ---------------- aggregation (H=128): relu(mean + yr) -> split bf16 hi/lo ----------------
__global__ void agg128_kernel(const __half* __restrict__ yl, const float* __restrict__ yrv,
                              __nv_bfloat16* __restrict__ xh, __nv_bfloat16* __restrict__ xl, int M)
{
    int gw = (blockIdx.x * blockDim.x + threadIdx.x) >> 5;
    int lane = threadIdx.x & 31;
    if (gw >= M) return;
    int beg = g_rowptr[gw], end = g_rowptr[gw + 1];
    float di = g_dinv[gw];

    float a0 = 0.f, a1 = 0.f, a2 = 0.f, a3 = 0.f;
    const __half* base = yl + lane * 4;
    int e = beg;
    for (; e + 2 <= end; e += 2) {
        int s0 = g_csr[e], s1 = g_csr[e + 1];
        uint2 r0 = *(const uint2*)(base + (size_t)s0 * 128);
        uint2 r1 = *(const uint2*)(base + (size_t)s1 * 128);
        float2 f0 = __half22float2(*(__half2*)&r0.x), f1 = __half22float2(*(__half2*)&r0.y);
        float2 g0 = __half22float2(*(__half2*)&r1.x), g1 = __half22float2(*(__half2*)&r1.y);
        a0 += f0.x + g0.x; a1 += f0.y + g0.y; a2 += f1.x + g1.x; a3 += f1.y + g1.y;
    }
    if (e < end) {
        int s0 = g_csr[e];
        uint2 r0 = *(const uint2*)(base + (size_t)s0 * 128);
        float2 f0 = __half22float2(*(__half2*)&r0.x), f1 = __half22float2(*(__half2*)&r0.y);
        a0 += f0.x; a1 += f0.y; a2 += f1.x; a3 += f1.y;
    }
    float4 r = *(const float4*)(yrv + (size_t)gw * 128 + lane * 4);
    float v0 = fmaxf(a0 * di + r.x, 0.f);
    float v1 = fmaxf(a1 * di + r.y, 0.f);
    float v2 = fmaxf(a2 * di + r.z, 0.f);
    float v3 = fmaxf(a3 * di + r.w, 0.f);

    __nv_bfloat16 h0 = __float2bfloat16_rn(v0), h1 = __float2bfloat16_rn(v1);
    __nv_bfloat16 h2 = __float2bfloat16_rn(v2), h3 = __float2bfloat16_rn(v3);
    __nv_bfloat162 ph0 = {h0, h1}, ph1 = {h2, h3};
    __nv_bfloat162 pl0 = {__float2bfloat16_rn(v0 - __bfloat162float(h0)),
                          __float2bfloat16_rn(v1 - __bfloat162float(h1))};
    __nv_bfloat162 pl1 = {__float2bfloat16_rn(v2 - __bfloat162float(h2)),
                          __float2bfloat16_rn(v3 - __bfloat162float(h3))};
    uint2 uh, ul;
    uh.x = *(uint32_t*)&ph0; uh.y = *(uint32_t*)&ph1;
    ul.x = *(uint32_t*)&pl0; ul.y = *(uint32_t*)&pl1;
    *(uint2*)(xh + (size_t)gw * 128 + lane * 4) = uh;
    *(uint2*)(xl + (size_t)gw * 128 + lane * 4) = ul;
}

// ---------------- aggregation (H=64) fused with classifier head ----------------
__global__ void agg64_head_kernel(const __half* __restrict__ yl, const float* __restrict__ yrv,
                                  const float* __restrict__ wout, const float* __restrict__ bout,
                                  float* __restrict__ out, int M)
{
    __shared__ float ws[256];
    __shared__ float bs[4];
    int t = threadIdx.x;
    ws[t] = wout[t];
    if (t < 4) bs[t] = bout[t];
    __syncthreads();
    int gw = blockIdx.x * 8 + (t >> 5);
    int lane = t & 31;
    if (gw >= M) return;
    int beg = g_rowptr[gw], end = g_rowptr[gw + 1];
    float di = g_dinv[gw];

    float a0 = 0.f, a1 = 0.f;
    const __half* base = yl + lane * 2;
    int e = beg;
    for (; e + 2 <= end; e += 2) {
        int s0 = g_csr[e], s1 = g_csr[e + 1];
        float2 f0 = __half22float2(*(const __half2*)(base + (size_t)s0 * 64));
        float2 f1 = __half22float2(*(const __half2*)(base + (size_t)s1 * 64));
        a0 += f0.x + f1.x; a1 += f0.y + f1.y;
    }
    if (e < end) {
        float2 f0 = __half22float2(*(const __half2*)(base + (size_t)g_csr[e] * 64));
        a0 += f0.x; a1 += f0.y;
    }
    float2 r = *(const float2*)(yrv + (size_t)gw * 64 + lane * 2);
    float v0 = fmaxf(a0 * di + r.x, 0.f);
    float v1 = fmaxf(a1 * di + r.y, 0.f);

    float acc[4];
#pragma unroll
    for (int c = 0; c < 4; c++)
        acc[c] = v0 * ws[(lane * 2) * 4 + c] + v1 * ws[(lane * 2 + 1) * 4 + c];
#pragma unroll
    for (int off = 16; off > 0; off >>= 1) {
#pragma unroll
        for (int c = 0; c < 4; c++)
            acc[c] += __shfl_xor_sync(0xFFFFFFFF, acc[c], off);
    }
    if (lane == 0) {
        float4 o = make_float4(acc[0] + bs[0], acc[1] + bs[1], acc[2] + bs[2], acc[3] + bs[3]);
        *(float4*)(out + (size_t)gw * 4) = o;
    }
}

// ---------------- launch ----------------
extern "C" void kernel_launch(void* const* d_in, const int* in_sizes, int n_in,
                              void* d_out, int out_size)
{
    (void)in_sizes; (void)n_in; (void)out_size;
    const float* x     = (const float*)d_in[0];
    const int*   ei    = (const int*)d_in[1];
    const float* w_l0  = (const float*)d_in[3];
    const float* w_r0  = (const float*)d_in[4];
    const float* b0    = (const float*)d_in[5];
    const float* w_l1  = (const float*)d_in[6];
    const float* w_r1  = (const float*)d_in[7];
    const float* b1    = (const float*)d_in[8];
    const float* w_l2  = (const float*)d_in[9];
    const float* w_r2  = (const float*)d_in[10];
    const float* b2    = (const float*)d_in[11];
    const float* w_out = (const float*)d_in[12];
    const float* b_out = (const float*)d_in[13];
    float* out = (float*)d_out;

    const int* srcp = ei;
    const int* dstp = ei + NE;

    __nv_bfloat16 *xhi, *xlo, *wt;
    __half* ylh;
    float* yrf;
    cudaGetSymbolAddress((void**)&xhi, g_xhi);
    cudaGetSymbolAddress((void**)&xlo, g_xlo);
    cudaGetSymbolAddress((void**)&ylh, g_ylh);
    cudaGetSymbolAddress((void**)&yrf, g_yrf);
    cudaGetSymbolAddress((void**)&wt,  g_wt);

    static cudaStream_t s2 = nullptr;
    static cudaEvent_t evFork = nullptr, evJoin = nullptr;
    if (!s2) {
        cudaStreamCreateWithFlags(&s2, cudaStreamNonBlocking);
        cudaEventCreateWithFlags(&evFork, cudaEventDisableTiming);
        cudaEventCreateWithFlags(&evJoin, cudaEventDisableTiming);
        cudaFuncSetAttribute(gemm_pers, cudaFuncAttributeMaxDynamicSharedMemorySize, 196608);
    }

    // ---- fork: CSR build on side stream ----
    cudaEventRecord(evFork, 0);
    cudaStreamWaitEvent(s2, evFork, 0);
    zero_cnt_kernel<<<(NN + 255) / 256, 256, 0, s2>>>();
    hist_kernel<<<(NE + 255) / 256, 256, 0, s2>>>(dstp);
    scan_kernel<<<1, 1024, 0, s2>>>();
    scatter_kernel<<<(NE + 255) / 256, 256, 0, s2>>>(srcp, dstp);
    cudaEventRecord(evJoin, s2);

    // ---- main stream: input split + weight preps + layer-0 GEMM ----
    conv0_kernel<<<(NN * 32 + 255) / 256, 256>>>(x, xhi, xlo);
    wprep_kernel<<<256, 256>>>(w_l0, w_r0, 128, wt);
    wprep_kernel<<<256, 256>>>(w_l1, w_r1, 128, wt + 65536);
    wprep_kernel<<<128, 256>>>(w_l2, w_r2, 64, wt + 131072);

    int ablk = (NN + 7) / 8;

    gemm_pers<<<dim3(74, 2), 256, 196608>>>(xhi, xlo, wt, b0, ylh, yrf, NN, 128);

    // ---- join: aggregation needs CSR ----
    cudaStreamWaitEvent(0, evJoin, 0);
    agg128_kernel<<<ablk, 256>>>(ylh, yrf, xhi, xlo, NN);
    // layer 1
    gemm_pers<<<dim3(74, 2), 256, 196608>>>(xhi, xlo, wt + 65536, b1, ylh, yrf, NN, 128);
    agg128_kernel<<<ablk, 256>>>(ylh, yrf, xhi, xlo, NN);
    // layer 2 (HO=64: cols 0..63 -> yl, 64..127 -> yr)
    gemm_pers<<<dim3(74, 1), 256, 196608>>>(xhi, xlo, wt + 131072, b2, ylh, yrf, NN, 64);
    // final aggregation + classifier head fused
    agg64_head_kernel<<<ablk, 256>>>(ylh, yrf, w_out, b_out, out, NN);
}